// round 12
// baseline (speedup 1.0000x reference)
#include <cuda_runtime.h>
#include <cuda_fp16.h>
#include <math.h>
#include <stdint.h>

#define BB 4096
#define DIM 2048
#define NE 8
#define NH 16
#define HD 128
#define N3 6144
#define N2 4096
#define SLOT_CAP 9216
#define SLOT_TILES 72
#define SCALE_F 0.08838834764831845f

#define TM 128
#define TN 128
#define KC 64
#define NCHUNK (DIM/KC)   // 32

// ---- smem layout: sTok @0 (1KB), then 2 stages.
// per stage: A16 (16KB) | B32 stage [64][132] f32 (33792B) | B16 (16KB)
#define OFF_A16 0
#define OFF_B32 16384
#define STAGE_LD 132
#define OFF_B16 (16384 + 33792)       // 50176
#define STAGE_B  (50176 + 16384)      // 66560
#define SMEM_TOTAL (1024 + 2*STAGE_B) // 134144

#define SWZ(o) ((o) ^ (((o) >> 3) & 0x70))

// ---------------- scratch (device globals; DEVICE-CODE ONLY — ATS trap!) ----
__device__ __half g_xh[(size_t)BB*DIM];
__device__ __half g_yh[(size_t)BB*DIM];
__device__ __half g_ahh[(size_t)BB*DIM];      // attn out f16, (d*NH+h) flatten
__device__ float  g_qs [(size_t)SLOT_CAP*DIM];
__device__ float  g_kvs[(size_t)SLOT_CAP*N2];
__device__ int    g_slot_tok[SLOT_CAP];
__device__ int    g_cnt[NE], g_off[NE+1], g_fill[NE];
__device__ int    g_e0[BB], g_e1[BB];
__device__ float  g_w0[BB], g_w1[BB];
__device__ int    g_s0[BB], g_s1[BB];

// ---------------- helpers ----------------
__device__ __forceinline__ uint32_t s2u(const void* p) {
    uint32_t a;
    asm("{ .reg .u64 t; cvta.to.shared.u64 t, %1; cvt.u32.u64 %0, t; }"
        : "=r"(a) : "l"(p));
    return a;
}
__device__ __forceinline__ void cpasync16(uint32_t dst, const void* src, int sz) {
    asm volatile("cp.async.cg.shared.global [%0], [%1], 16, %2;"
                 :: "r"(dst), "l"(src), "r"(sz) : "memory");
}
#define CP_COMMIT() asm volatile("cp.async.commit_group;" ::: "memory")
#define CP_WAIT(n)  asm volatile("cp.async.wait_group %0;" :: "n"(n) : "memory")
#define LDMX4(r, a) \
    asm volatile("ldmatrix.sync.aligned.m8n8.x4.shared.b16 {%0,%1,%2,%3}, [%4];" \
                 : "=r"((r)[0]), "=r"((r)[1]), "=r"((r)[2]), "=r"((r)[3]) : "r"(a))
__device__ __forceinline__ void mma_f16(float* c, const uint32_t* a,
                                        uint32_t b0, uint32_t b1) {
    asm volatile(
        "mma.sync.aligned.m16n8k16.row.col.f32.f16.f16.f32 "
        "{%0,%1,%2,%3}, {%4,%5,%6,%7}, {%8,%9}, {%0,%1,%2,%3};"
        : "+f"(c[0]), "+f"(c[1]), "+f"(c[2]), "+f"(c[3])
        : "r"(a[0]), "r"(a[1]), "r"(a[2]), "r"(a[3]), "r"(b0), "r"(b1));
}
__device__ __forceinline__ uint32_t pack2(float a, float b) {
    __half2 h = __floats2half2_rn(a, b);
    return *(uint32_t*)&h;
}

// ---------------- setup ----------------
__global__ void k_init() {
    int i = blockIdx.x * 256 + threadIdx.x;
    if (i < SLOT_CAP) g_slot_tok[i] = -1;
    if (i < NE) { g_cnt[i] = 0; g_fill[i] = 0; }
}

__global__ void k_gate(const float* __restrict__ x,
                       const float* __restrict__ Wg,
                       const float* __restrict__ bg) {
    int warp = (blockIdx.x * blockDim.x + threadIdx.x) >> 5;
    int lane = threadIdx.x & 31;
    if (warp >= BB) return;
    const float* xr = x + (size_t)warp * DIM;
    float acc[NE];
#pragma unroll
    for (int e = 0; e < NE; e++) acc[e] = 0.f;
    for (int d = lane; d < DIM; d += 32) {
        float xv = xr[d];
        const float4* w4 = reinterpret_cast<const float4*>(Wg + (size_t)d * NE);
        float4 a = w4[0], b = w4[1];
        acc[0] += xv * a.x; acc[1] += xv * a.y; acc[2] += xv * a.z; acc[3] += xv * a.w;
        acc[4] += xv * b.x; acc[5] += xv * b.y; acc[6] += xv * b.z; acc[7] += xv * b.w;
    }
#pragma unroll
    for (int e = 0; e < NE; e++) {
#pragma unroll
        for (int o = 16; o > 0; o >>= 1) acc[e] += __shfl_down_sync(0xffffffffu, acc[e], o);
    }
    if (lane == 0) {
        float z[NE], p[NE];
        float m = -1e30f;
#pragma unroll
        for (int e = 0; e < NE; e++) { z[e] = acc[e] + bg[e]; m = fmaxf(m, z[e]); }
        float s = 0.f;
#pragma unroll
        for (int e = 0; e < NE; e++) { p[e] = expf(z[e] - m); s += p[e]; }
        float inv = 1.f / s;
        int e0 = 0; float v0 = p[0];
#pragma unroll
        for (int e = 1; e < NE; e++) if (p[e] > v0) { v0 = p[e]; e0 = e; }
        int e1 = (e0 == 0) ? 1 : 0; float v1 = p[e1];
#pragma unroll
        for (int e = 0; e < NE; e++) if (e != e0 && p[e] > v1) { v1 = p[e]; e1 = e; }
        g_e0[warp] = e0; g_w0[warp] = v0 * inv;
        g_e1[warp] = e1; g_w1[warp] = v1 * inv;
        atomicAdd(&g_cnt[e0], 1);
        atomicAdd(&g_cnt[e1], 1);
    }
}

__global__ void k_offsets() {
    int o = 0;
    for (int e = 0; e < NE; e++) {
        g_off[e] = o;
        o += (g_cnt[e] + TM - 1) & ~(TM - 1);
    }
    g_off[NE] = o;
}

__global__ void k_scatter() {
    int b = blockIdx.x * blockDim.x + threadIdx.x;
    if (b >= BB) return;
    int e0 = g_e0[b];
    int s0 = g_off[e0] + atomicAdd(&g_fill[e0], 1);
    g_slot_tok[s0] = b;  g_s0[b] = s0;
    int e1 = g_e1[b];
    int s1 = g_off[e1] + atomicAdd(&g_fill[e1], 1);
    g_slot_tok[s1] = b;  g_s1[b] = s1;
}

// ---------------- prepass: convert x,y to f16 (A side only; tiny) ----------
__global__ void k_split_xy(const float* __restrict__ x, const float* __restrict__ y) {
    size_t i = ((size_t)blockIdx.x * 256 + threadIdx.x) * 4;
    if (i >= (size_t)BB * DIM) return;
    float4 vx = *(const float4*)(x + i);
    float4 vy = *(const float4*)(y + i);
    __half2* ox = (__half2*)(g_xh + i);
    ox[0] = __floats2half2_rn(vx.x, vx.y);
    ox[1] = __floats2half2_rn(vx.z, vx.w);
    __half2* oy = (__half2*)(g_yh + i);
    oy[0] = __floats2half2_rn(vy.x, vy.y);
    oy[1] = __floats2half2_rn(vy.z, vy.w);
}

// ---------------- GEMM: f16 MMA, in-kernel B f32->f16 transpose-convert -----
// grid (rowtiles fastest, coltiles second) for B L2 reuse.
// mode 0: grid(72, 48): y<32 -> kv path (B = We cols DIM+128y), y>=32 -> q path
// mode 2: grid(32, 16): A = attn f16, B = Wp, out = dout + bp
__global__ __launch_bounds__(256, 1)
void k_mm(const float* __restrict__ We, const float* __restrict__ Wp,
          const float* __restrict__ bp, float* __restrict__ dout, int mode)
{
    extern __shared__ char sm[];
    const int tid = threadIdx.x, wid = tid >> 5, lane = tid & 31;
    const int row0 = blockIdx.x * TM;

    const __half* Ah;
    const float* Bsrc;           // f32, [k][n] row-major, row stride ldb
    long ldb;
    bool gather;
    float* Cb; int ldc; int ccol0;
    if (mode == 2) {
        int col0 = blockIdx.y * TN;
        Ah = g_ahh;
        Bsrc = Wp + col0; ldb = DIM;
        gather = false; Cb = dout; ldc = DIM; ccol0 = col0;
    } else {
        if (row0 >= g_off[NE]) return;
        int e = 0;
        while (e < NE - 1 && row0 >= g_off[e + 1]) e++;
        bool qpath = blockIdx.y >= 32;
        int col0 = (qpath ? blockIdx.y - 32 : blockIdx.y) * TN;
        int n0 = qpath ? col0 : (DIM + col0);
        Ah = qpath ? g_yh : g_xh;
        Bsrc = We + (size_t)e * DIM * N3 + n0; ldb = N3;
        gather = true;
        Cb = qpath ? g_qs : g_kvs;
        ldc = qpath ? DIM : N2;
        ccol0 = col0;
    }

    int* sTok = (int*)sm;
    if (tid < TM) sTok[tid] = gather ? g_slot_tok[row0 + tid] : (row0 + tid);
    __syncthreads();
    const uint32_t sbU = s2u(sm) + 1024;

    // A f16 load slots: q = tid*4+i -> row q>>3, 16B col q&7
    int r16[4], c16[4], t16[4];
#pragma unroll
    for (int i = 0; i < 4; i++) {
        int q = tid * 4 + i;
        r16[i] = q >> 3; c16[i] = q & 7;
        t16[i] = sTok[r16[i]];
    }

    auto load_chunk = [&](int c, int s) {
        const int k0 = c * KC;
        const uint32_t base = sbU + s * STAGE_B;
        // A f16 (pre-converted, k-major)
#pragma unroll
        for (int i = 0; i < 4; i++) {
            uint32_t dsw = SWZ((uint32_t)(r16[i] * 128 + c16[i] * 16));
            int tok = t16[i];
            int ok = (tok >= 0) ? 16 : 0;
            cpasync16(base + OFF_A16 + dsw,
                      Ah + (size_t)(ok ? tok : 0) * DIM + k0 + c16[i] * 8, ok);
        }
        // B f32 stage: warp w -> rows 8w..8w+7, lane -> 4 floats
        {
            const float* wp = Bsrc + (size_t)(k0 + 8 * wid) * ldb + 4 * lane;
#pragma unroll
            for (int p = 0; p < 8; p++) {
                uint32_t d = base + OFF_B32
                           + (uint32_t)((8 * wid + p) * STAGE_LD + 4 * lane) * 4;
                cpasync16(d, wp + (size_t)p * ldb, 16);
            }
        }
        CP_COMMIT();
    };

    const int warpRow = (wid & 1) * 64;
    const int warpCol = (wid >> 1) * 32;
    const int fr = lane & 15, fh = (lane >> 4) * 16;
    const int bn = tid >> 1, bh = (tid & 1) * 32;   // convert assignment

    float acc[4][4][4];
#pragma unroll
    for (int i = 0; i < 4; i++)
#pragma unroll
        for (int j = 0; j < 4; j++)
#pragma unroll
            for (int t = 0; t < 4; t++) acc[i][j][t] = 0.f;

    load_chunk(0, 0);
    for (int c = 0; c < NCHUNK; c++) {
        const int st = c & 1;
        if (c + 1 < NCHUNK) {
            load_chunk(c + 1, st ^ 1);
            CP_WAIT(1);
        } else {
            CP_WAIT(0);
        }
        __syncthreads();
        const uint32_t base = sbU + st * STAGE_B;
        // transpose-convert B f32 stage -> swizzled f16 [n][k]
        {
            const float* stage = (const float*)(sm + 1024 + st * STAGE_B + OFF_B32);
#pragma unroll
            for (int g = 0; g < 8; g++) {
                int k4 = bh + 4 * g;
                float f0 = stage[(k4 + 0) * STAGE_LD + bn];
                float f1 = stage[(k4 + 1) * STAGE_LD + bn];
                float f2 = stage[(k4 + 2) * STAGE_LD + bn];
                float f3 = stage[(k4 + 3) * STAGE_LD + bn];
                uint2 hv;
                hv.x = pack2(f0, f1);
                hv.y = pack2(f2, f3);
                *(uint2*)(sm + 1024 + st * STAGE_B + OFF_B16
                          + SWZ((uint32_t)(bn * 128 + 2 * k4))) = hv;
            }
        }
        __syncthreads();
        // MMA
#pragma unroll
        for (int s = 0; s < 4; s++) {
            const uint32_t kb = (uint32_t)(s * 32 + fh);
            uint32_t aF[4][4], bF[2][4];
#pragma unroll
            for (int i = 0; i < 4; i++) {
                uint32_t off = SWZ((uint32_t)((warpRow + 16 * i + fr) * 128) + kb);
                LDMX4(aF[i], base + OFF_A16 + off);
            }
#pragma unroll
            for (int jj = 0; jj < 2; jj++) {
                uint32_t off = SWZ((uint32_t)((warpCol + 16 * jj + fr) * 128) + kb);
                LDMX4(bF[jj], base + OFF_B16 + off);
            }
#pragma unroll
            for (int i = 0; i < 4; i++)
#pragma unroll
                for (int j = 0; j < 4; j++) {
                    int jj = j >> 1, hs = j & 1;
                    mma_f16(acc[i][j], aF[i], bF[jj][hs], bF[jj][hs + 2]);
                }
        }
        __syncthreads();
    }

    // epilogue (fragment mapping validated rounds 8-11)
    const int qrow = lane >> 2, klane = (lane & 3) * 2;
#pragma unroll
    for (int i = 0; i < 4; i++) {
        int r0 = row0 + warpRow + 16 * i + qrow;
#pragma unroll
        for (int j = 0; j < 4; j++) {
            int cc = ccol0 + warpCol + 8 * j + klane;
            float b0 = 0.f, b1 = 0.f;
            if (mode == 2) { b0 = bp[cc]; b1 = bp[cc + 1]; }
            *(float2*)(Cb + (size_t)r0 * ldc + cc) =
                make_float2(acc[i][j][0] + b0, acc[i][j][1] + b1);
            *(float2*)(Cb + (size_t)(r0 + 8) * ldc + cc) =
                make_float2(acc[i][j][2] + b0, acc[i][j][3] + b1);
        }
    }
}

// ---------------- per-token 16x16 head-attention; writes f16 output --------
__global__ void k_attn() {
    int b = blockIdx.x;
    __shared__ float sQ[DIM], sK[DIM], sV[DIM];
    __shared__ float sS[NH][NH + 1];
    int tid = threadIdx.x;
    int s0 = g_s0[b], s1 = g_s1[b];
    float w0 = g_w0[b], w1 = g_w1[b];
    const float* q0 = g_qs + (size_t)s0 * DIM;
    const float* q1 = g_qs + (size_t)s1 * DIM;
    const float* kv0 = g_kvs + (size_t)s0 * N2;
    const float* kv1 = g_kvs + (size_t)s1 * N2;
    for (int i = tid; i < DIM; i += 256) {
        sQ[i] = w0 * q0[i] + w1 * q1[i];
        sK[i] = w0 * kv0[i] + w1 * kv1[i];
        sV[i] = w0 * kv0[DIM + i] + w1 * kv1[DIM + i];
    }
    __syncthreads();
    {
        int h = tid >> 4, g = tid & 15;
        float s = 0.f;
        int qb0 = h * HD, kb0 = g * HD;
#pragma unroll 8
        for (int dd = 0; dd < HD; dd++) {
            int d = (dd + tid) & (HD - 1);
            s += sQ[qb0 + d] * sK[kb0 + d];
        }
        sS[h][g] = s * SCALE_F;
    }
    __syncthreads();
    if (tid < NH) {
        float m = -1e30f;
#pragma unroll
        for (int g = 0; g < NH; g++) m = fmaxf(m, sS[tid][g]);
        float sum = 0.f;
#pragma unroll
        for (int g = 0; g < NH; g++) { float p = expf(sS[tid][g] - m); sS[tid][g] = p; sum += p; }
        float inv = 1.f / sum;
#pragma unroll
        for (int g = 0; g < NH; g++) sS[tid][g] *= inv;
    }
    __syncthreads();
    size_t ob = (size_t)b * DIM;
    for (int i = tid; i < DIM; i += 256) {
        int h = i >> 7, d = i & (HD - 1);
        float o = 0.f;
#pragma unroll
        for (int g = 0; g < NH; g++) o += sS[h][g] * sV[g * HD + d];
        g_ahh[ob + (size_t)d * NH + h] = __float2half_rn(o);  // swapaxes flatten
    }
}

// ---------------- launch ----------------
extern "C" void kernel_launch(void* const* d_in, const int* in_sizes, int n_in,
                              void* d_out, int out_size) {
    const float *x = nullptr, *y = nullptr, *We = nullptr, *Wg = nullptr;
    const float *bg = nullptr, *Wp = nullptr, *bp = nullptr;
    for (int i = 0; i < n_in; i++) {
        const float* p = (const float*)d_in[i];
        switch (in_sizes[i]) {
            case 100663296: We = p; break;
            case 8388608:   if (!x) x = p; else y = p; break;
            case 4194304:   Wp = p; break;
            case 16384:     Wg = p; break;
            case 2048:      bp = p; break;
            case 8:         bg = p; break;
            default: break;
        }
    }
    float* out = (float*)d_out;

    cudaFuncSetAttribute(k_mm, cudaFuncAttributeMaxDynamicSharedMemorySize, SMEM_TOTAL);

    k_init<<<36, 256>>>();
    k_gate<<<BB / 8, 256>>>(x, Wg, bg);
    k_offsets<<<1, 1>>>();
    k_scatter<<<16, 256>>>();
    k_split_xy<<<(BB * DIM / 4 + 255) / 256, 256>>>(x, y);
    {   // fused kv+q routed GEMMs (rowtiles fastest)
        dim3 grid(SLOT_TILES, 48);
        k_mm<<<grid, 256, SMEM_TOTAL>>>(We, Wp, bp, out, 0);
    }
    k_attn<<<BB, 256>>>();
    {   // projection
        dim3 grid(BB / TM, DIM / TN);
        k_mm<<<grid, 256, SMEM_TOTAL>>>(We, Wp, bp, out, 2);
    }
}

// round 13
// speedup vs baseline: 1.3951x; 1.3951x over previous
#include <cuda_runtime.h>
#include <cuda_fp16.h>
#include <math.h>
#include <stdint.h>

#define BB 4096
#define DIM 2048
#define NE 8
#define NH 16
#define HD 128
#define N3 6144
#define N2 4096
#define SLOT_CAP 9216
#define SLOT_TILES 72
#define SCALE_F 0.08838834764831845f

#define TM 128
#define TN 128
#define KC 64
#define NCHUNK (DIM/KC)   // 32

// ---- smem layout: sTok @0 (1KB), stages @1024; per stage A16|B16 (16KB each)
#define OFF_A16 0
#define OFF_B16 16384
#define STAGE_B 32768
#define SMEM_TOTAL (1024 + 2*STAGE_B)   // 66560

#define SWZ(o) ((o) ^ (((o) >> 3) & 0x70))

// ---------------- scratch (device globals; DEVICE-CODE ONLY — ATS trap!) ----
__device__ __half g_WeT[(size_t)NE*N3*DIM];   // We^T f16 [e][n][k]
__device__ __half g_WpT[(size_t)DIM*DIM];     // Wp^T f16 [n][k]
__device__ __half g_xh[(size_t)BB*DIM];
__device__ __half g_yh[(size_t)BB*DIM];
__device__ __half g_ahh[(size_t)BB*DIM];      // attn out f16, (d*NH+h) flatten
__device__ __half g_qs [(size_t)SLOT_CAP*DIM];   // per-slot q (f16)
__device__ __half g_kvs[(size_t)SLOT_CAP*N2];    // per-slot k|v (f16)
__device__ int    g_slot_tok[SLOT_CAP];
__device__ int    g_cnt[NE], g_off[NE+1], g_fill[NE];
__device__ int    g_e0[BB], g_e1[BB];
__device__ float  g_w0[BB], g_w1[BB];
__device__ int    g_s0[BB], g_s1[BB];

// ---------------- helpers ----------------
__device__ __forceinline__ uint32_t s2u(const void* p) {
    uint32_t a;
    asm("{ .reg .u64 t; cvta.to.shared.u64 t, %1; cvt.u32.u64 %0, t; }"
        : "=r"(a) : "l"(p));
    return a;
}
__device__ __forceinline__ void cpasync16(uint32_t dst, const void* src, int sz) {
    asm volatile("cp.async.cg.shared.global [%0], [%1], 16, %2;"
                 :: "r"(dst), "l"(src), "r"(sz) : "memory");
}
#define CP_COMMIT() asm volatile("cp.async.commit_group;" ::: "memory")
#define CP_WAIT(n)  asm volatile("cp.async.wait_group %0;" :: "n"(n) : "memory")
#define LDMX4(r, a) \
    asm volatile("ldmatrix.sync.aligned.m8n8.x4.shared.b16 {%0,%1,%2,%3}, [%4];" \
                 : "=r"((r)[0]), "=r"((r)[1]), "=r"((r)[2]), "=r"((r)[3]) : "r"(a))
__device__ __forceinline__ void mma_f16(float* c, const uint32_t* a,
                                        uint32_t b0, uint32_t b1) {
    asm volatile(
        "mma.sync.aligned.m16n8k16.row.col.f32.f16.f16.f32 "
        "{%0,%1,%2,%3}, {%4,%5,%6,%7}, {%8,%9}, {%0,%1,%2,%3};"
        : "+f"(c[0]), "+f"(c[1]), "+f"(c[2]), "+f"(c[3])
        : "r"(a[0]), "r"(a[1]), "r"(a[2]), "r"(a[3]), "r"(b0), "r"(b1));
}
__device__ __forceinline__ uint32_t pack2(float a, float b) {
    __half2 h = __floats2half2_rn(a, b);
    return *(uint32_t*)&h;
}

// ---------------- setup ----------------
__global__ void k_init() {
    int i = blockIdx.x * 256 + threadIdx.x;
    if (i < SLOT_CAP) g_slot_tok[i] = -1;
    if (i < NE) { g_cnt[i] = 0; g_fill[i] = 0; }
}

__global__ void k_gate(const float* __restrict__ x,
                       const float* __restrict__ Wg,
                       const float* __restrict__ bg) {
    int warp = (blockIdx.x * blockDim.x + threadIdx.x) >> 5;
    int lane = threadIdx.x & 31;
    if (warp >= BB) return;
    const float* xr = x + (size_t)warp * DIM;
    float acc[NE];
#pragma unroll
    for (int e = 0; e < NE; e++) acc[e] = 0.f;
    for (int d = lane; d < DIM; d += 32) {
        float xv = xr[d];
        const float4* w4 = reinterpret_cast<const float4*>(Wg + (size_t)d * NE);
        float4 a = w4[0], b = w4[1];
        acc[0] += xv * a.x; acc[1] += xv * a.y; acc[2] += xv * a.z; acc[3] += xv * a.w;
        acc[4] += xv * b.x; acc[5] += xv * b.y; acc[6] += xv * b.z; acc[7] += xv * b.w;
    }
#pragma unroll
    for (int e = 0; e < NE; e++) {
#pragma unroll
        for (int o = 16; o > 0; o >>= 1) acc[e] += __shfl_down_sync(0xffffffffu, acc[e], o);
    }
    if (lane == 0) {
        float z[NE], p[NE];
        float m = -1e30f;
#pragma unroll
        for (int e = 0; e < NE; e++) { z[e] = acc[e] + bg[e]; m = fmaxf(m, z[e]); }
        float s = 0.f;
#pragma unroll
        for (int e = 0; e < NE; e++) { p[e] = expf(z[e] - m); s += p[e]; }
        float inv = 1.f / s;
        int e0 = 0; float v0 = p[0];
#pragma unroll
        for (int e = 1; e < NE; e++) if (p[e] > v0) { v0 = p[e]; e0 = e; }
        int e1 = (e0 == 0) ? 1 : 0; float v1 = p[e1];
#pragma unroll
        for (int e = 0; e < NE; e++) if (e != e0 && p[e] > v1) { v1 = p[e]; e1 = e; }
        g_e0[warp] = e0; g_w0[warp] = v0 * inv;
        g_e1[warp] = e1; g_w1[warp] = v1 * inv;
        atomicAdd(&g_cnt[e0], 1);
        atomicAdd(&g_cnt[e1], 1);
    }
}

__global__ void k_offsets() {
    int o = 0;
    for (int e = 0; e < NE; e++) {
        g_off[e] = o;
        o += (g_cnt[e] + TM - 1) & ~(TM - 1);
    }
    g_off[NE] = o;
}

__global__ void k_scatter() {
    int b = blockIdx.x * blockDim.x + threadIdx.x;
    if (b >= BB) return;
    int e0 = g_e0[b];
    int s0 = g_off[e0] + atomicAdd(&g_fill[e0], 1);
    g_slot_tok[s0] = b;  g_s0[b] = s0;
    int e1 = g_e1[b];
    int s1 = g_off[e1] + atomicAdd(&g_fill[e1], 1);
    g_slot_tok[s1] = b;  g_s1[b] = s1;
}

// ---------------- prepass: convert x,y to f16 ----------------
__global__ void k_split_xy(const float* __restrict__ x, const float* __restrict__ y) {
    size_t i = ((size_t)blockIdx.x * 256 + threadIdx.x) * 4;
    if (i >= (size_t)BB * DIM) return;
    float4 vx = *(const float4*)(x + i);
    float4 vy = *(const float4*)(y + i);
    __half2* ox = (__half2*)(g_xh + i);
    ox[0] = __floats2half2_rn(vx.x, vx.y);
    ox[1] = __floats2half2_rn(vx.z, vx.w);
    __half2* oy = (__half2*)(g_yh + i);
    oy[0] = __floats2half2_rn(vy.x, vy.y);
    oy[1] = __floats2half2_rn(vy.z, vy.w);
}

// ---------------- prepass: transpose + convert weights to f16 --------------
// Tiles 32n x 64k: 128B coalesced reads AND 128B coalesced writes.
// which=0: We (8x [2048 x 6144]) -> [e][n][k];  which=1: Wp -> [n][k]
__global__ void k_tsplit(const float* __restrict__ src, int C, int which) {
    __shared__ float tile[32][65];    // [n-local][k-local]
    int c0 = blockIdx.x * 32;         // n origin
    int r0 = blockIdx.y * 64;         // k origin
    int e = blockIdx.z;
    int tid = threadIdx.x;
    int tx = tid & 31, ty = tid >> 5; // tx: n-local, ty: 0..7
    const float* s = src + (size_t)e * DIM * C;
#pragma unroll
    for (int rr = ty; rr < 64; rr += 8)
        tile[tx][rr] = s[(size_t)(r0 + rr) * C + c0 + tx];
    __syncthreads();
    __half* oh = which ? g_WpT : (g_WeT + (size_t)e * N3 * DIM);
#pragma unroll
    for (int it = 0; it < 4; it++) {
        int idx = tid + 256 * it;     // 0..1023 half2-packs
        int n = idx >> 5;             // 0..31
        int kp = (idx & 31) * 2;      // 0..62
        uint32_t v = pack2(tile[n][kp], tile[n][kp + 1]);
        *(uint32_t*)(oh + (size_t)(c0 + n) * DIM + r0 + kp) = v;
    }
}

// ---------------- GEMM: pure f16, cp.async pipelined, ldmatrix --------------
// mode 0 (grid.x=48): x<32 -> kv path, x>=32 -> q path (routed); C = f16
// mode 2 (grid.x=16): A=attn f16, B=WpT, out=dout(f32)+bp
__global__ __launch_bounds__(256, 2)
void k_mm(const float* __restrict__ bp, float* __restrict__ dout, int mode)
{
    extern __shared__ char sm[];
    const int tid = threadIdx.x, wid = tid >> 5, lane = tid & 31;
    const int row0 = blockIdx.y * TM;

    const __half *Ah, *Bh;
    bool gather;
    __half* Ch = nullptr; float* Cf = nullptr;
    int ldc; int ccol0;
    if (mode == 2) {
        int col0 = blockIdx.x * TN;
        Ah = g_ahh;
        Bh = g_WpT + (size_t)col0 * DIM;
        gather = false; Cf = dout; ldc = DIM; ccol0 = col0;
    } else {
        if (row0 >= g_off[NE]) return;
        int e = 0;
        while (e < NE - 1 && row0 >= g_off[e + 1]) e++;
        bool qpath = blockIdx.x >= 32;
        int col0 = (qpath ? blockIdx.x - 32 : blockIdx.x) * TN;
        int n0 = qpath ? col0 : (DIM + col0);
        Ah = qpath ? g_yh : g_xh;
        Bh = g_WeT + ((size_t)e * N3 + n0) * DIM;
        gather = true;
        Ch = qpath ? g_qs : g_kvs;
        ldc = qpath ? DIM : N2;
        ccol0 = col0;
    }

    int* sTok = (int*)sm;
    if (tid < TM) sTok[tid] = gather ? g_slot_tok[row0 + tid] : (row0 + tid);
    __syncthreads();
    const uint32_t sbU = s2u(sm) + 1024;

    // load slots: q = tid*4+i -> row q>>3, 16B col q&7
    int r16[4], c16[4], t16[4];
#pragma unroll
    for (int i = 0; i < 4; i++) {
        int q = tid * 4 + i;
        r16[i] = q >> 3; c16[i] = q & 7;
        t16[i] = sTok[r16[i]];
    }

    auto load_chunk = [&](int c, int s) {
        const int k0 = c * KC;
        const uint32_t base = sbU + s * STAGE_B;
#pragma unroll
        for (int i = 0; i < 4; i++) {
            uint32_t dsw = SWZ((uint32_t)(r16[i] * 128 + c16[i] * 16));
            int tok = t16[i];
            int ok = (tok >= 0) ? 16 : 0;
            cpasync16(base + OFF_A16 + dsw,
                      Ah + (size_t)(ok ? tok : 0) * DIM + k0 + c16[i] * 8, ok);
            cpasync16(base + OFF_B16 + dsw,
                      Bh + (size_t)r16[i] * DIM + k0 + c16[i] * 8, 16);
        }
        CP_COMMIT();
    };

    const int warpRow = (wid & 1) * 64;
    const int warpCol = (wid >> 1) * 32;
    const int fr = lane & 15, fh = (lane >> 4) * 16;

    float acc[4][4][4];
#pragma unroll
    for (int i = 0; i < 4; i++)
#pragma unroll
        for (int j = 0; j < 4; j++)
#pragma unroll
            for (int t = 0; t < 4; t++) acc[i][j][t] = 0.f;

    load_chunk(0, 0);
    for (int c = 0; c < NCHUNK; c++) {
        const int st = c & 1;
        if (c + 1 < NCHUNK) {
            load_chunk(c + 1, st ^ 1);
            CP_WAIT(1);
        } else {
            CP_WAIT(0);
        }
        __syncthreads();
        const uint32_t base = sbU + st * STAGE_B;
#pragma unroll
        for (int s = 0; s < 4; s++) {
            const uint32_t kb = (uint32_t)(s * 32 + fh);
            uint32_t aF[4][4], bF[2][4];
#pragma unroll
            for (int i = 0; i < 4; i++) {
                uint32_t off = SWZ((uint32_t)((warpRow + 16 * i + fr) * 128) + kb);
                LDMX4(aF[i], base + OFF_A16 + off);
            }
#pragma unroll
            for (int jj = 0; jj < 2; jj++) {
                uint32_t off = SWZ((uint32_t)((warpCol + 16 * jj + fr) * 128) + kb);
                LDMX4(bF[jj], base + OFF_B16 + off);
            }
#pragma unroll
            for (int i = 0; i < 4; i++)
#pragma unroll
                for (int j = 0; j < 4; j++) {
                    int jj = j >> 1, hs = j & 1;
                    mma_f16(acc[i][j], aF[i], bF[jj][hs], bF[jj][hs + 2]);
                }
        }
        __syncthreads();
    }

    // epilogue (fragment mapping validated rounds 8-11)
    const int qrow = lane >> 2, klane = (lane & 3) * 2;
#pragma unroll
    for (int i = 0; i < 4; i++) {
        int r0 = row0 + warpRow + 16 * i + qrow;
#pragma unroll
        for (int j = 0; j < 4; j++) {
            int cc = ccol0 + warpCol + 8 * j + klane;
            if (mode == 2) {
                float b0 = bp[cc], b1 = bp[cc + 1];
                *(float2*)(Cf + (size_t)r0 * ldc + cc) =
                    make_float2(acc[i][j][0] + b0, acc[i][j][1] + b1);
                *(float2*)(Cf + (size_t)(r0 + 8) * ldc + cc) =
                    make_float2(acc[i][j][2] + b0, acc[i][j][3] + b1);
            } else {
                *(uint32_t*)(Ch + (size_t)r0 * ldc + cc) =
                    pack2(acc[i][j][0], acc[i][j][1]);
                *(uint32_t*)(Ch + (size_t)(r0 + 8) * ldc + cc) =
                    pack2(acc[i][j][2], acc[i][j][3]);
            }
        }
    }
}

// ---------------- per-token 16x16 head-attention; f16 in, f16 out ----------
__global__ void k_attn() {
    int b = blockIdx.x;
    __shared__ float sQ[DIM], sK[DIM], sV[DIM];
    __shared__ float sS[NH][NH + 1];
    int tid = threadIdx.x;
    int s0 = g_s0[b], s1 = g_s1[b];
    float w0 = g_w0[b], w1 = g_w1[b];
    const __half* q0 = g_qs + (size_t)s0 * DIM;
    const __half* q1 = g_qs + (size_t)s1 * DIM;
    const __half* kv0 = g_kvs + (size_t)s0 * N2;
    const __half* kv1 = g_kvs + (size_t)s1 * N2;
    for (int i = tid; i < DIM; i += 256) {
        sQ[i] = w0 * __half2float(q0[i]) + w1 * __half2float(q1[i]);
        sK[i] = w0 * __half2float(kv0[i]) + w1 * __half2float(kv1[i]);
        sV[i] = w0 * __half2float(kv0[DIM + i]) + w1 * __half2float(kv1[DIM + i]);
    }
    __syncthreads();
    {
        int h = tid >> 4, g = tid & 15;
        float s = 0.f;
        int qb0 = h * HD, kb0 = g * HD;
#pragma unroll 8
        for (int dd = 0; dd < HD; dd++) {
            int d = (dd + tid) & (HD - 1);
            s += sQ[qb0 + d] * sK[kb0 + d];
        }
        sS[h][g] = s * SCALE_F;
    }
    __syncthreads();
    if (tid < NH) {
        float m = -1e30f;
#pragma unroll
        for (int g = 0; g < NH; g++) m = fmaxf(m, sS[tid][g]);
        float sum = 0.f;
#pragma unroll
        for (int g = 0; g < NH; g++) { float p = expf(sS[tid][g] - m); sS[tid][g] = p; sum += p; }
        float inv = 1.f / sum;
#pragma unroll
        for (int g = 0; g < NH; g++) sS[tid][g] *= inv;
    }
    __syncthreads();
    size_t ob = (size_t)b * DIM;
    for (int i = tid; i < DIM; i += 256) {
        int h = i >> 7, d = i & (HD - 1);
        float o = 0.f;
#pragma unroll
        for (int g = 0; g < NH; g++) o += sS[h][g] * sV[g * HD + d];
        g_ahh[ob + (size_t)d * NH + h] = __float2half_rn(o);  // swapaxes flatten
    }
}

// ---------------- launch ----------------
extern "C" void kernel_launch(void* const* d_in, const int* in_sizes, int n_in,
                              void* d_out, int out_size) {
    const float *x = nullptr, *y = nullptr, *We = nullptr, *Wg = nullptr;
    const float *bg = nullptr, *Wp = nullptr, *bp = nullptr;
    for (int i = 0; i < n_in; i++) {
        const float* p = (const float*)d_in[i];
        switch (in_sizes[i]) {
            case 100663296: We = p; break;
            case 8388608:   if (!x) x = p; else y = p; break;
            case 4194304:   Wp = p; break;
            case 16384:     Wg = p; break;
            case 2048:      bp = p; break;
            case 8:         bg = p; break;
            default: break;
        }
    }
    float* out = (float*)d_out;

    cudaFuncSetAttribute(k_mm, cudaFuncAttributeMaxDynamicSharedMemorySize, SMEM_TOTAL);

    k_init<<<36, 256>>>();
    k_gate<<<BB / 8, 256>>>(x, Wg, bg);
    k_offsets<<<1, 1>>>();
    k_scatter<<<16, 256>>>();
    k_split_xy<<<(BB * DIM / 4 + 255) / 256, 256>>>(x, y);
    {
        dim3 grid(N3 / 32, DIM / 64, NE);
        k_tsplit<<<grid, 256>>>(We, N3, 0);
    }
    {
        dim3 grid(DIM / 32, DIM / 64, 1);
        k_tsplit<<<grid, 256>>>(Wp, DIM, 1);
    }
    {   // fused kv+q routed GEMMs
        dim3 grid(48, SLOT_TILES);
        k_mm<<<grid, 256, SMEM_TOTAL>>>(bp, out, 0);
    }
    k_attn<<<BB, 256>>>();
    {   // projection
        dim3 grid(DIM / TN, BB / TM);
        k_mm<<<grid, 256, SMEM_TOTAL>>>(bp, out, 2);
    }
}